// round 3
// baseline (speedup 1.0000x reference)
#include <cuda_runtime.h>
#include <math.h>

#define BB 8
#define NN 256
#define DD 128
#define NROWS (BB * NN)          /* 2048 node rows        */
#define NEDGE (BB * NN * NN)     /* 524288 edge rows      */

/* Scratch (allocation-free: __device__ globals) */
__device__ __align__(16) float g_w[NEDGE];        /* 2 MB: edge norms            */
__device__ __align__(16) float g_z[NROWS * DD];   /* 1 MB: relu(linear) output   */
__device__ __align__(16) float g_scale[DD];
__device__ __align__(16) float g_shift[DD];

/* ------------------------------------------------------------------ */
/* K1: stream e -> out_e copy fused with per-edge L2 norm.            */
/* One warp per edge row (128 floats = 32 lanes x float4).            */
/* ------------------------------------------------------------------ */
__global__ void k1_norm_copy(const float4* __restrict__ e4,
                             float4* __restrict__ oute4)
{
    unsigned gt   = blockIdx.x * blockDim.x + threadIdx.x;
    unsigned row  = gt >> 5;
    unsigned lane = gt & 31;
    size_t idx = (size_t)row * 32 + lane;

    float4 v = e4[idx];
    oute4[idx] = v;

    float s = v.x * v.x + v.y * v.y + v.z * v.z + v.w * v.w;
#pragma unroll
    for (int o = 16; o; o >>= 1) s += __shfl_xor_sync(0xffffffffu, s, o);
    if (lane == 0) g_w[row] = sqrtf(s);
}

/* ------------------------------------------------------------------ */
/* K2: per (batch, 8-row tile): softmax(w) -> agg = w@h -> y = h+agg  */
/*     -> z = relu(y @ W^T + b).                                       */
/* 256 blocks x 256 threads. h[b] tile and transposed W live in smem. */
/* ------------------------------------------------------------------ */
#define SM_H   (NN * DD)          /* 32768 floats */
#define SM_WT  (DD * 129)         /* 16512 floats, stride 129 = conflict-free */
#define SM_PT  (NN * 8)           /* 2048  floats, p transposed [j][r]        */
#define SM_Y   (8 * DD)           /* 1024  floats */
#define SM_AG  (16 * DD)          /* 2048  floats (two halves)                */
#define SMEM2  ((SM_H + SM_WT + SM_PT + SM_Y + SM_AG) * sizeof(float))

__global__ void __launch_bounds__(256, 1)
k2_agg_linear(const float* __restrict__ h,
              const float* __restrict__ W,
              const float* __restrict__ bias)
{
    extern __shared__ float sm[];
    float* h_s  = sm;                     /* [256][128]            */
    float* wt_s = h_s  + SM_H;            /* [128][129] W^T padded */
    float* pt_s = wt_s + SM_WT;           /* [256 j][8 r]          */
    float* y_s  = pt_s + SM_PT;           /* [8][128]              */
    float* ag_s = y_s  + SM_Y;            /* [2 half][8][128]      */

    const int t  = threadIdx.x;
    const int b  = blockIdx.x >> 5;
    const int i0 = (blockIdx.x & 31) * 8;

    /* Phase A: load h[b] (coalesced float4) */
    {
        const float4* hb = reinterpret_cast<const float4*>(h + (size_t)b * NN * DD);
        float4* h_s4 = reinterpret_cast<float4*>(h_s);
#pragma unroll
        for (int it = 0; it < 32; it++)
            h_s4[t + it * 256] = hb[t + it * 256];
    }
    /* Load W transposed: wt_s[dd*129 + k] = W[k*128 + dd].
       Gmem read coalesced; smem write banks = (dd+k)%32 -> conflict-free. */
#pragma unroll
    for (int it = 0; it < 64; it++) {
        int idx = t + it * 256;
        float v = W[idx];
        int k = idx >> 7, dd = idx & 127;
        wt_s[dd * 129 + k] = v;
    }

    /* Phase B: softmax over j for 8 rows; warp w owns row r=w.
       Results stored transposed: pt_s[j*8 + r]. */
    {
        int wid = t >> 5, lane = t & 31;
        int gi = (b * NN + i0 + wid) * NN;
        float v[8];
#pragma unroll
        for (int q = 0; q < 8; q++) v[q] = g_w[gi + q * 32 + lane];
        float mx = v[0];
#pragma unroll
        for (int q = 1; q < 8; q++) mx = fmaxf(mx, v[q]);
#pragma unroll
        for (int o = 16; o; o >>= 1) mx = fmaxf(mx, __shfl_xor_sync(0xffffffffu, mx, o));
        float s = 0.f;
#pragma unroll
        for (int q = 0; q < 8; q++) { v[q] = __expf(v[q] - mx); s += v[q]; }
#pragma unroll
        for (int o = 16; o; o >>= 1) s += __shfl_xor_sync(0xffffffffu, s, o);
        float inv = 1.0f / s;
#pragma unroll
        for (int q = 0; q < 8; q++)
            pt_s[(q * 32 + lane) * 8 + wid] = v[q] * inv;
    }
    __syncthreads();

    /* Phase C: agg[r][d] = sum_j p[r][j] * h[j][d].
       128 d-threads x 2 j-halves, 8-row register blocking,
       p read as two LDS.128 broadcasts per j. */
    {
        int d = t & 127, half = t >> 7;
        float acc[8] = {0.f, 0.f, 0.f, 0.f, 0.f, 0.f, 0.f, 0.f};
        const float*  hp = h_s + half * 128 * DD + d;
        const float4* pp = reinterpret_cast<const float4*>(pt_s) + half * 256;
#pragma unroll 4
        for (int jj = 0; jj < 128; jj++) {
            float  hv = hp[jj * DD];
            float4 p0 = pp[jj * 2];
            float4 p1 = pp[jj * 2 + 1];
            acc[0] += p0.x * hv; acc[1] += p0.y * hv;
            acc[2] += p0.z * hv; acc[3] += p0.w * hv;
            acc[4] += p1.x * hv; acc[5] += p1.y * hv;
            acc[6] += p1.z * hv; acc[7] += p1.w * hv;
        }
#pragma unroll
        for (int r = 0; r < 8; r++)
            ag_s[(half * 8 + r) * 128 + d] = acc[r];
    }
    __syncthreads();

    /* y = h + agg (combine halves) */
    if (t < 128) {
#pragma unroll
        for (int r = 0; r < 8; r++)
            y_s[r * 128 + t] = h_s[(i0 + r) * 128 + t]
                             + ag_s[r * 128 + t] + ag_s[(8 + r) * 128 + t];
    }
    __syncthreads();

    /* Phase D: z[r][k] = relu(sum_dd y[r][dd] * W[k][dd] + b[k]).
       128 k-threads x 2 row-groups, 4-row register blocking. */
    {
        int k = t & 127, g = t >> 7;
        float bv = bias[k];
        float a0 = 0.f, a1 = 0.f, a2 = 0.f, a3 = 0.f;
        const float* yb = y_s + g * 4 * 128;
#pragma unroll 4
        for (int dd = 0; dd < 128; dd++) {
            float wv = wt_s[dd * 129 + k];
            a0 += yb[0 * 128 + dd] * wv;
            a1 += yb[1 * 128 + dd] * wv;
            a2 += yb[2 * 128 + dd] * wv;
            a3 += yb[3 * 128 + dd] * wv;
        }
        int rowbase = b * NN + i0 + g * 4;
        g_z[(rowbase + 0) * DD + k] = fmaxf(a0 + bv, 0.f);
        g_z[(rowbase + 1) * DD + k] = fmaxf(a1 + bv, 0.f);
        g_z[(rowbase + 2) * DD + k] = fmaxf(a2 + bv, 0.f);
        g_z[(rowbase + 3) * DD + k] = fmaxf(a3 + bv, 0.f);
    }
}

/* ------------------------------------------------------------------ */
/* K3: BN statistics, one block per feature k (deterministic).        */
/* ------------------------------------------------------------------ */
__global__ void k3_bnstats(const float* __restrict__ gamma,
                           const float* __restrict__ beta)
{
    __shared__ float rs[8], rs2[8];
    int k = blockIdx.x, t = threadIdx.x;
    float s = 0.f, s2 = 0.f;
    for (int row = t; row < NROWS; row += 256) {
        float v = g_z[row * DD + k];
        s += v; s2 += v * v;
    }
#pragma unroll
    for (int o = 16; o; o >>= 1) {
        s  += __shfl_xor_sync(0xffffffffu, s,  o);
        s2 += __shfl_xor_sync(0xffffffffu, s2, o);
    }
    if ((t & 31) == 0) { rs[t >> 5] = s; rs2[t >> 5] = s2; }
    __syncthreads();
    if (t == 0) {
        s = 0.f; s2 = 0.f;
#pragma unroll
        for (int i = 0; i < 8; i++) { s += rs[i]; s2 += rs2[i]; }
        float mean = s * (1.0f / NROWS);
        float var  = s2 * (1.0f / NROWS) - mean * mean;
        float sc = gamma[k] * rsqrtf(var + 1e-5f);
        g_scale[k] = sc;
        g_shift[k] = beta[k] - mean * sc;
    }
}

/* ------------------------------------------------------------------ */
/* K4: out_h = z*scale + shift + h  (vectorized elementwise)          */
/* ------------------------------------------------------------------ */
__global__ void k4_apply(const float4* __restrict__ h4,
                         float4* __restrict__ out4)
{
    int idx = blockIdx.x * 256 + threadIdx.x;   /* 0..65535 float4s */
    float4 z  = reinterpret_cast<const float4*>(g_z)[idx];
    float4 hv = h4[idx];
    int c = idx & 31;                           /* 128/4 = 32 float4 features */
    float4 sc = reinterpret_cast<const float4*>(g_scale)[c];
    float4 sh = reinterpret_cast<const float4*>(g_shift)[c];
    float4 o;
    o.x = z.x * sc.x + sh.x + hv.x;
    o.y = z.y * sc.y + sh.y + hv.y;
    o.z = z.z * sc.z + sh.z + hv.z;
    o.w = z.w * sc.w + sh.w + hv.w;
    out4[idx] = o;
}

/* ------------------------------------------------------------------ */
extern "C" void kernel_launch(void* const* d_in, const int* in_sizes, int n_in,
                              void* d_out, int out_size)
{
    const float* h     = (const float*)d_in[0];   /* (8,256,128)     */
    const float* e     = (const float*)d_in[1];   /* (8,256,256,128) */
    const float* W     = (const float*)d_in[2];   /* (128,128)       */
    const float* bias  = (const float*)d_in[3];   /* (128,)          */
    const float* gamma = (const float*)d_in[4];   /* (128,)          */
    const float* beta  = (const float*)d_in[5];   /* (128,)          */

    float* out_h = (float*)d_out;                 /* first output: h_new */
    float* out_e = out_h + (size_t)NROWS * DD;    /* second output: e    */

    cudaFuncSetAttribute(k2_agg_linear,
                         cudaFuncAttributeMaxDynamicSharedMemorySize,
                         (int)SMEM2);

    /* K1: 524288 edge rows, 1 warp each -> 65536 blocks of 256 */
    k1_norm_copy<<<NEDGE / 8, 256>>>(
        reinterpret_cast<const float4*>(e),
        reinterpret_cast<float4*>(out_e));

    /* K2: 8 batches x 32 tiles of 8 rows */
    k2_agg_linear<<<256, 256, SMEM2>>>(h, W, bias);

    /* K3: one block per feature */
    k3_bnstats<<<DD, 256>>>(gamma, beta);

    /* K4: 262144 floats = 65536 float4s */
    k4_apply<<<256, 256>>>(reinterpret_cast<const float4*>(h), out_h ? reinterpret_cast<float4*>(out_h) : nullptr);
}